// round 3
// baseline (speedup 1.0000x reference)
#include <cuda_runtime.h>
#include <cstdint>

// SquareRotationalLayer ring-unroll gather for H=W=512 (even).
// out[b,c,dif,j] = in[b,c, r(dif,j), col(dif,j)] with the 9-segment ring layout.
//
// For ring `dif` (0..H/2-1):
//   i  = (H-1)/2 - dif          (top-left corner coordinate)
//   el = 2*dif + 1              (H even)
//   jm = i + el = W - 1 - i     (bottom-right corner coordinate)
// Segment boundaries (prefix sums of [i, el, 2i, el, 2i, el, 2i, el, i]),
// total 4H-4; cols [4H-4, 4H) wrap to cols [0,4).

__device__ __forceinline__ int ring_src_idx(int dif, int j, int H) {
    const int i  = ((H - 1) >> 1) - dif;
    const int el = 2 * dif + 1;
    const int jm = i + el;            // == W-1-i
    const int n  = 4 * H - 4;
    if (j >= n) j -= n;               // wraparound copy of first 4 elements

    const int b1 = i;
    const int b2 = b1 + el;
    const int b3 = b2 + 2 * i;
    const int b4 = b3 + el;
    const int b5 = b4 + 2 * i;
    const int b6 = b5 + el;
    const int b7 = b6 + 2 * i;
    const int b8 = b7 + el;

    int r, c;
    if (j < b1)      { r = i;             c = i;             }  // corner rep
    else if (j < b2) { r = i;             c = i + (j - b1);  }  // top row ->
    else if (j < b3) { r = i;             c = jm;            }  // TR corner rep
    else if (j < b4) { r = i + (j - b3);  c = jm;            }  // right col v
    else if (j < b5) { r = jm;            c = jm;            }  // BR corner rep
    else if (j < b6) { r = jm;            c = jm - (j - b5); }  // bottom row <-
    else if (j < b7) { r = jm;            c = i;             }  // BL corner rep
    else if (j < b8) { r = jm - (j - b7); c = i;             }  // left col ^
    else             { r = i;             c = i;             }  // corner rep
    return r * H + c;  // W == H
}

__global__ __launch_bounds__(512, 4)
void SqRL_ring_gather_kernel(const float* __restrict__ in,
                             float* __restrict__ out,
                             int H) {
    const int dif   = blockIdx.x;              // ring / output row, 0..H/2-1
    const int plane = blockIdx.y;              // fused B*C plane
    const int j0    = threadIdx.x << 2;        // 4 cols per thread, 512 thr * 4 = 2048

    const float* __restrict__ src = in + (size_t)plane * H * H;

    // 4 independent gathers -> MLP=4, then one coalesced 128-bit store.
    const int s0 = ring_src_idx(dif, j0 + 0, H);
    const int s1 = ring_src_idx(dif, j0 + 1, H);
    const int s2 = ring_src_idx(dif, j0 + 2, H);
    const int s3 = ring_src_idx(dif, j0 + 3, H);

    float4 v;
    v.x = __ldg(src + s0);
    v.y = __ldg(src + s1);
    v.z = __ldg(src + s2);
    v.w = __ldg(src + s3);

    const size_t out_off = (((size_t)plane * (H >> 1) + dif) * (size_t)(4 * H)) + j0;
    *reinterpret_cast<float4*>(out + out_off) = v;
}

extern "C" void kernel_launch(void* const* d_in, const int* in_sizes, int n_in,
                              void* d_out, int out_size) {
    const float* x = (const float*)d_in[0];
    float* out = (float*)d_out;

    const int H  = 512;                      // fixed problem shape (16,32,512,512)
    const int BC = in_sizes[0] / (H * H);    // 16*32 = 512 planes

    dim3 grid(H / 2, BC);                    // (256, 512)
    dim3 block(512);                         // 512 thr * 4 cols = 2048 = 4H
    SqRL_ring_gather_kernel<<<grid, block>>>(x, out, H);
}